// round 2
// baseline (speedup 1.0000x reference)
#include <cuda_runtime.h>
#include <cstdint>
#include <cstddef>

#define GXD 480
#define GYD 360
#define NSEG (GXD*GYD)
#define NHD 32
#define MAXN 131072
#define EPSF 1e-5f

// ---------------- scratch (device globals; no allocation allowed) ----------------
__device__ float    g_y1[(size_t)MAXN * 64];
__device__ float    g_y2[(size_t)MAXN * 128];
__device__ float    g_y3[(size_t)MAXN * 256];
__device__ unsigned g_seg[(size_t)NSEG * 512];
__device__ int      g_occ[NSEG];
// stats: offsets 0(C=7), 7(C=64), 71(C=128), 199(C=256); total 455
__device__ float    g_sum[512];
__device__ float    g_sq[512];
__device__ float    g_scale[512];
__device__ float    g_shift[512];

// order-preserving float<->uint mapping for atomicMax-based segment max
__device__ __forceinline__ unsigned fenc(float f) {
    unsigned u = __float_as_uint(f);
    return (u & 0x80000000u) ? ~u : (u | 0x80000000u);
}
__device__ __forceinline__ float fdec(unsigned k) {
    unsigned u = (k & 0x80000000u) ? (k & 0x7FFFFFFFu) : ~k;
    return __uint_as_float(u);
}

// ---------------- clear scratch for one sample ----------------
__global__ void clear_kernel() {
    size_t i = (size_t)blockIdx.x * blockDim.x + threadIdx.x;
    size_t stride = (size_t)gridDim.x * blockDim.x;
    const size_t n4 = (size_t)NSEG * 512 / 4;
    uint4 z = {0u, 0u, 0u, 0u};
    uint4* s4 = (uint4*)g_seg;
    for (size_t j = i; j < n4; j += stride) s4[j] = z;
    for (size_t j = i; j < (size_t)NSEG; j += stride) g_occ[j] = 0;
    if (i < 512) { g_sum[i] = 0.f; g_sq[i] = 0.f; }
}

// ---------------- per-column sum / sumsq (C must divide blockDim.x) ----------------
__global__ void colstats_kernel(const float* __restrict__ X, int n, int C,
                                float* __restrict__ gsum, float* __restrict__ gsq) {
    int tid = threadIdx.x;
    int nt = blockDim.x;
    int col = tid % C;
    int rpb = nt / C;
    int sub = tid / C;
    float s = 0.f, q = 0.f;
    for (long long r = (long long)blockIdx.x * rpb + sub; r < n; r += (long long)gridDim.x * rpb) {
        float v = X[r * (long long)C + col];   // addr = base*C + tid -> fully coalesced
        s += v; q += v * v;
    }
    __shared__ float ss[256];
    __shared__ float qq[256];
    ss[tid] = s; qq[tid] = q;
    __syncthreads();
    if (sub == 0) {
        for (int t = tid + C; t < nt; t += C) { s += ss[t]; q += qq[t]; }
        atomicAdd(&gsum[col], s);
        atomicAdd(&gsq[col], q);
    }
}

// ---------------- stats -> (scale, shift) ----------------
__global__ void finalize_kernel(const float* __restrict__ sum, const float* __restrict__ sq,
                                const float* __restrict__ g, const float* __restrict__ b,
                                float* __restrict__ scale, float* __restrict__ shift,
                                int C, float invn) {
    int i = blockIdx.x * blockDim.x + threadIdx.x;
    if (i < C) {
        float m = sum[i] * invn;
        float v = sq[i] * invn - m * m;
        float sc = g[i] * rsqrtf(v + EPSF);
        scale[i] = sc;
        shift[i] = b[i] - m * sc;
    }
}

// ---------------- layer1: [n,7] -> [n,64], thread-per-point ----------------
__global__ void __launch_bounds__(256) gemm1_kernel(
    const float* __restrict__ X, const float* __restrict__ sc, const float* __restrict__ sh,
    const float* __restrict__ W, const float* __restrict__ bias,
    float* __restrict__ Y, int n) {
    __shared__ float Ws[7][64];
    __shared__ float bs[64];
    __shared__ float scs[7], shs[7];
    int tid = threadIdx.x;
    for (int i = tid; i < 448; i += 256) Ws[i / 64][i % 64] = W[i];
    if (tid < 64) bs[tid] = bias[tid];
    if (tid < 7) { scs[tid] = sc[tid]; shs[tid] = sh[tid]; }
    __syncthreads();
    int r = blockIdx.x * 256 + tid;
    if (r >= n) return;
    float a[7];
#pragma unroll
    for (int f = 0; f < 7; f++) a[f] = X[(size_t)r * 7 + f] * scs[f] + shs[f];  // bn0, no relu
    float acc[64];
#pragma unroll
    for (int c = 0; c < 64; c++) {
        float v = bs[c];
#pragma unroll
        for (int f = 0; f < 7; f++) v += a[f] * Ws[f][c];
        acc[c] = v;
    }
    float4* yo = (float4*)&Y[(size_t)r * 64];
#pragma unroll
    for (int c4 = 0; c4 < 16; c4++)
        yo[c4] = make_float4(acc[c4 * 4], acc[c4 * 4 + 1], acc[c4 * 4 + 2], acc[c4 * 4 + 3]);
}

// ---------------- tiled GEMM: Y[n,CO] = relu(X*scale+shift)[n,K] @ W[K,CO] + b ----------------
// BM=64 BN=64 BK=16, 256 threads, 4x4 per-thread microtile.
// EPI=0: store Y.  EPI=1: atomicMax scatter into segment buffer (layer 4).
template <int EPI>
__global__ void __launch_bounds__(256) gemm_tiled(
    const float* __restrict__ X, int K,
    const float* __restrict__ scale, const float* __restrict__ shift,
    const float* __restrict__ W, int CO, const float* __restrict__ bias,
    float* __restrict__ Y, const int* __restrict__ xy, unsigned* __restrict__ seg, int n) {
    __shared__ float As[16][68];
    __shared__ float Bs[16][64];
    extern __shared__ float dyn[];
    float* scs = dyn;
    float* shs = dyn + K;
    int tid = threadIdx.x;
    for (int i = tid; i < K; i += 256) { scs[i] = scale[i]; shs[i] = shift[i]; }
    __syncthreads();

    int row0 = blockIdx.y * 64, col0 = blockIdx.x * 64;
    int tx = tid & 15, ty = tid >> 4;
    int arow = tid >> 2, ak = (tid & 3) * 4;
    int bk = tid >> 4, bc = (tid & 15) * 4;
    float acc[4][4] = {};

    for (int k0 = 0; k0 < K; k0 += 16) {
        int gr = row0 + arow;
        float4 av = {0.f, 0.f, 0.f, 0.f};
        if (gr < n) av = *(const float4*)&X[(size_t)gr * K + k0 + ak];
        As[ak + 0][arow] = fmaxf(av.x * scs[k0 + ak + 0] + shs[k0 + ak + 0], 0.f);
        As[ak + 1][arow] = fmaxf(av.y * scs[k0 + ak + 1] + shs[k0 + ak + 1], 0.f);
        As[ak + 2][arow] = fmaxf(av.z * scs[k0 + ak + 2] + shs[k0 + ak + 2], 0.f);
        As[ak + 3][arow] = fmaxf(av.w * scs[k0 + ak + 3] + shs[k0 + ak + 3], 0.f);
        float4 bv = *(const float4*)&W[(size_t)(k0 + bk) * CO + col0 + bc];
        *(float4*)&Bs[bk][bc] = bv;
        __syncthreads();
#pragma unroll
        for (int kk = 0; kk < 16; kk++) {
            float4 a = *(const float4*)&As[kk][ty * 4];
            float4 b = *(const float4*)&Bs[kk][tx * 4];
            float ar[4] = {a.x, a.y, a.z, a.w};
            float br[4] = {b.x, b.y, b.z, b.w};
#pragma unroll
            for (int i = 0; i < 4; i++)
#pragma unroll
                for (int j = 0; j < 4; j++) acc[i][j] += ar[i] * br[j];
        }
        __syncthreads();
    }

    if (EPI == 0) {
#pragma unroll
        for (int i = 0; i < 4; i++) {
            int gr = row0 + ty * 4 + i;
            if (gr < n) {
                int c = col0 + tx * 4;
                float4 o = make_float4(acc[i][0] + bias[c], acc[i][1] + bias[c + 1],
                                       acc[i][2] + bias[c + 2], acc[i][3] + bias[c + 3]);
                *(float4*)&Y[(size_t)gr * CO + c] = o;
            }
        }
    } else {
#pragma unroll
        for (int i = 0; i < 4; i++) {
            int gr = row0 + ty * 4 + i;
            if (gr < n) {
                int id = xy[(size_t)gr * 2] * GYD + xy[(size_t)gr * 2 + 1];
                unsigned* srow = seg + (size_t)id * 512;
#pragma unroll
                for (int j = 0; j < 4; j++) {
                    int c = col0 + tx * 4 + j;
                    atomicMax(&srow[c], fenc(acc[i][j] + bias[c]));
                }
            }
        }
    }
}

// ---------------- occupancy marking ----------------
__global__ void mark_occ(const int* __restrict__ xy, int n) {
    int i = blockIdx.x * 256 + threadIdx.x;
    if (i < n) g_occ[xy[(size_t)i * 2] * GYD + xy[(size_t)i * 2 + 1]] = 1;
}

// ---------------- head: [NSEG,512] seg keys -> out[c*NSEG + s] ----------------
// BM=128 BN=32 BK=16, 256 threads, 4x4 per-thread microtile.
__global__ void __launch_bounds__(256) head_kernel(
    const unsigned* __restrict__ seg, const int* __restrict__ occ,
    const float* __restrict__ W5, const float* __restrict__ b5, float* __restrict__ out) {
    __shared__ float As[16][132];
    __shared__ float Bs[16][32];
    __shared__ int occs[128];
    __shared__ float b5s[32];
    int tid = threadIdx.x;
    int row0 = blockIdx.x * 128;
    if (tid < 128) occs[tid] = occ[row0 + tid];
    if (tid < 32) b5s[tid] = b5[tid];
    __syncthreads();
    int tx = tid & 7, ty = tid >> 3;
    float acc[4][4] = {};

    for (int k0 = 0; k0 < 512; k0 += 16) {
#pragma unroll
        for (int l = 0; l < 2; l++) {
            int idx4 = tid + l * 256;
            int row = idx4 >> 2;
            int k4 = (idx4 & 3) * 4;
            uint4 kv = *(const uint4*)&seg[(size_t)(row0 + row) * 512 + k0 + k4];
            float4 av;
            if (occs[row]) {
                av = make_float4(fdec(kv.x), fdec(kv.y), fdec(kv.z), fdec(kv.w));
            } else {
                av = make_float4(0.f, 0.f, 0.f, 0.f);
            }
            As[k4 + 0][row] = av.x;
            As[k4 + 1][row] = av.y;
            As[k4 + 2][row] = av.z;
            As[k4 + 3][row] = av.w;
        }
        if (tid < 128) {
            int krow = tid >> 3, c4 = (tid & 7) * 4;
            *(float4*)&Bs[krow][c4] = *(const float4*)&W5[(size_t)(k0 + krow) * 32 + c4];
        }
        __syncthreads();
#pragma unroll
        for (int kk = 0; kk < 16; kk++) {
            float4 a = *(const float4*)&As[kk][ty * 4];
            float4 b = *(const float4*)&Bs[kk][tx * 4];
            float ar[4] = {a.x, a.y, a.z, a.w};
            float br[4] = {b.x, b.y, b.z, b.w};
#pragma unroll
            for (int i = 0; i < 4; i++)
#pragma unroll
                for (int j = 0; j < 4; j++) acc[i][j] += ar[i] * br[j];
        }
        __syncthreads();
    }
#pragma unroll
    for (int i = 0; i < 4; i++) {
        int lr = ty * 4 + i;
        int gr = row0 + lr;
        int oc = occs[lr];
#pragma unroll
        for (int j = 0; j < 4; j++) {
            int c = tx * 4 + j;
            float v = oc ? fmaxf(acc[i][j] + b5s[c], 0.f) : 0.f;
            out[(size_t)c * NSEG + gr] = v;   // out[c][gx][gy] with s = gx*GY+gy
        }
    }
}

// ---------------- host orchestration ----------------
extern "C" void kernel_launch(void* const* d_in, const int* in_sizes, int n_in,
                              void* d_out, int out_size) {
    const float* pt   = (const float*)d_in[0];
    const int*   xy   = (const int*)d_in[1];
    const float* bn0g = (const float*)d_in[2];
    const float* bn0b = (const float*)d_in[3];
    const float* W1   = (const float*)d_in[4];
    const float* b1   = (const float*)d_in[5];
    const float* bn1g = (const float*)d_in[6];
    const float* bn1b = (const float*)d_in[7];
    const float* W2   = (const float*)d_in[8];
    const float* b2   = (const float*)d_in[9];
    const float* bn2g = (const float*)d_in[10];
    const float* bn2b = (const float*)d_in[11];
    const float* W3   = (const float*)d_in[12];
    const float* b3   = (const float*)d_in[13];
    const float* bn3g = (const float*)d_in[14];
    const float* bn3b = (const float*)d_in[15];
    const float* W4   = (const float*)d_in[16];
    const float* b4   = (const float*)d_in[17];
    const float* W5   = (const float*)d_in[18];
    const float* b5   = (const float*)d_in[19];

    int B = out_size / (NHD * NSEG);
    if (B < 1) B = 1;
    int n = in_sizes[0] / (B * 7);
    float invn = 1.f / (float)n;

    float *y1, *y2, *y3, *sum, *sq, *sc, *sh;
    unsigned* seg;
    int* occ;
    cudaGetSymbolAddress((void**)&y1, g_y1);
    cudaGetSymbolAddress((void**)&y2, g_y2);
    cudaGetSymbolAddress((void**)&y3, g_y3);
    cudaGetSymbolAddress((void**)&seg, g_seg);
    cudaGetSymbolAddress((void**)&occ, g_occ);
    cudaGetSymbolAddress((void**)&sum, g_sum);
    cudaGetSymbolAddress((void**)&sq, g_sq);
    cudaGetSymbolAddress((void**)&sc, g_scale);
    cudaGetSymbolAddress((void**)&sh, g_shift);

    int nblk64 = (n + 63) / 64;

    for (int b = 0; b < B; b++) {
        const float* fea = pt + (size_t)b * n * 7;
        const int* xyb = xy + (size_t)b * n * 2;
        float* outb = (float*)d_out + (size_t)b * NHD * NSEG;

        clear_kernel<<<4096, 256>>>();

        // bn0 stats
        colstats_kernel<<<512, 224>>>(fea, n, 7, sum + 0, sq + 0);
        finalize_kernel<<<1, 32>>>(sum + 0, sq + 0, bn0g, bn0b, sc + 0, sh + 0, 7, invn);

        // layer 1: 7 -> 64
        gemm1_kernel<<<(n + 255) / 256, 256>>>(fea, sc + 0, sh + 0, W1, b1, y1, n);
        colstats_kernel<<<512, 256>>>(y1, n, 64, sum + 7, sq + 7);
        finalize_kernel<<<1, 64>>>(sum + 7, sq + 7, bn1g, bn1b, sc + 7, sh + 7, 64, invn);

        // layer 2: 64 -> 128
        gemm_tiled<0><<<dim3(2, nblk64), 256, 2 * 64 * sizeof(float)>>>(
            y1, 64, sc + 7, sh + 7, W2, 128, b2, y2, nullptr, nullptr, n);
        colstats_kernel<<<512, 256>>>(y2, n, 128, sum + 71, sq + 71);
        finalize_kernel<<<1, 128>>>(sum + 71, sq + 71, bn2g, bn2b, sc + 71, sh + 71, 128, invn);

        // layer 3: 128 -> 256
        gemm_tiled<0><<<dim3(4, nblk64), 256, 2 * 128 * sizeof(float)>>>(
            y2, 128, sc + 71, sh + 71, W3, 256, b3, y3, nullptr, nullptr, n);
        colstats_kernel<<<512, 256>>>(y3, n, 256, sum + 199, sq + 199);
        finalize_kernel<<<2, 128>>>(sum + 199, sq + 199, bn3g, bn3b, sc + 199, sh + 199, 256, invn);

        // occupancy + layer 4 (256 -> 512) with fused segment-max scatter
        mark_occ<<<(n + 255) / 256, 256>>>(xyb, n);
        gemm_tiled<1><<<dim3(8, nblk64), 256, 2 * 256 * sizeof(float)>>>(
            y3, 256, sc + 199, sh + 199, W4, 512, b4, nullptr, xyb, seg, n);

        // head: 512 -> 32, masked, transposed write
        head_kernel<<<NSEG / 128, 256>>>(seg, occ, W5, b5, outb);
    }
}

// round 3
// speedup vs baseline: 1.6359x; 1.6359x over previous
#include <cuda_runtime.h>
#include <cstdint>
#include <cstddef>

#define GXD 480
#define GYD 360
#define NSEG (GXD*GYD)
#define NHD 32
#define MAXN 131072
#define EPSF 1e-5f

// ---------------- scratch (device globals; no allocation allowed) ----------------
__device__ float    g_y1[(size_t)MAXN * 64];
__device__ float    g_y2[(size_t)MAXN * 128];
__device__ float    g_y3[(size_t)MAXN * 256];
__device__ unsigned g_seg[(size_t)NSEG * 512];
__device__ int      g_occ[NSEG];
__device__ float    g_sum[512];
__device__ float    g_sq[512];
__device__ float    g_scale[512];
__device__ float    g_shift[512];

// order-preserving float<->uint mapping for atomicMax-based segment max
__device__ __forceinline__ unsigned fenc(float f) {
    unsigned u = __float_as_uint(f);
    return (u & 0x80000000u) ? ~u : (u | 0x80000000u);
}
__device__ __forceinline__ float fdec(unsigned k) {
    unsigned u = (k & 0x80000000u) ? (k & 0x7FFFFFFFu) : ~k;
    return __uint_as_float(u);
}

__device__ __forceinline__ unsigned tf32cvt(float f) {
    unsigned u;
    asm("cvt.rna.tf32.f32 %0, %1;" : "=r"(u) : "f"(f));
    return u;
}

__device__ __forceinline__ void mma_tf32(float c[4], const unsigned a[4], const unsigned b[2]) {
    asm volatile(
        "mma.sync.aligned.m16n8k8.row.col.f32.tf32.tf32.f32 "
        "{%0,%1,%2,%3}, {%4,%5,%6,%7}, {%8,%9}, {%0,%1,%2,%3};"
        : "+f"(c[0]), "+f"(c[1]), "+f"(c[2]), "+f"(c[3])
        : "r"(a[0]), "r"(a[1]), "r"(a[2]), "r"(a[3]), "r"(b[0]), "r"(b[1]));
}

// ---------------- clear scratch for one sample ----------------
__global__ void clear_kernel() {
    size_t i = (size_t)blockIdx.x * blockDim.x + threadIdx.x;
    size_t stride = (size_t)gridDim.x * blockDim.x;
    const size_t n4 = (size_t)NSEG * 512 / 4;
    uint4 z = {0u, 0u, 0u, 0u};
    uint4* s4 = (uint4*)g_seg;
    for (size_t j = i; j < n4; j += stride) s4[j] = z;
    for (size_t j = i; j < (size_t)NSEG; j += stride) g_occ[j] = 0;
    if (i < 512) { g_sum[i] = 0.f; g_sq[i] = 0.f; }
}

// ---------------- per-column sum / sumsq (C must divide blockDim.x) ----------------
__global__ void colstats_kernel(const float* __restrict__ X, int n, int C,
                                float* __restrict__ gsum, float* __restrict__ gsq) {
    int tid = threadIdx.x;
    int nt = blockDim.x;
    int col = tid % C;
    int rpb = nt / C;
    int sub = tid / C;
    float s = 0.f, q = 0.f;
    for (long long r = (long long)blockIdx.x * rpb + sub; r < n; r += (long long)gridDim.x * rpb) {
        float v = X[r * (long long)C + col];
        s += v; q += v * v;
    }
    __shared__ float ss[256];
    __shared__ float qq[256];
    ss[tid] = s; qq[tid] = q;
    __syncthreads();
    if (sub == 0) {
        for (int t = tid + C; t < nt; t += C) { s += ss[t]; q += qq[t]; }
        atomicAdd(&gsum[col], s);
        atomicAdd(&gsq[col], q);
    }
}

// ---------------- stats -> (scale, shift) ----------------
__global__ void finalize_kernel(const float* __restrict__ sum, const float* __restrict__ sq,
                                const float* __restrict__ g, const float* __restrict__ b,
                                float* __restrict__ scale, float* __restrict__ shift,
                                int C, float invn) {
    int i = blockIdx.x * blockDim.x + threadIdx.x;
    if (i < C) {
        float m = sum[i] * invn;
        float v = sq[i] * invn - m * m;
        float sc = g[i] * rsqrtf(v + EPSF);
        scale[i] = sc;
        shift[i] = b[i] - m * sc;
    }
}

// ---------------- layer1: [n,7] -> [n,64], thread-per-point, fp32 ----------------
__global__ void __launch_bounds__(256) gemm1_kernel(
    const float* __restrict__ X, const float* __restrict__ sc, const float* __restrict__ sh,
    const float* __restrict__ W, const float* __restrict__ bias,
    float* __restrict__ Y, int n) {
    __shared__ float Ws[7][64];
    __shared__ float bs[64];
    __shared__ float scs[7], shs[7];
    int tid = threadIdx.x;
    for (int i = tid; i < 448; i += 256) Ws[i / 64][i % 64] = W[i];
    if (tid < 64) bs[tid] = bias[tid];
    if (tid < 7) { scs[tid] = sc[tid]; shs[tid] = sh[tid]; }
    __syncthreads();
    int r = blockIdx.x * 256 + tid;
    if (r >= n) return;
    float a[7];
#pragma unroll
    for (int f = 0; f < 7; f++) a[f] = X[(size_t)r * 7 + f] * scs[f] + shs[f];  // bn0, no relu
    float acc[64];
#pragma unroll
    for (int c = 0; c < 64; c++) {
        float v = bs[c];
#pragma unroll
        for (int f = 0; f < 7; f++) v += a[f] * Ws[f][c];
        acc[c] = v;
    }
    float4* yo = (float4*)&Y[(size_t)r * 64];
#pragma unroll
    for (int c4 = 0; c4 < 16; c4++)
        yo[c4] = make_float4(acc[c4 * 4], acc[c4 * 4 + 1], acc[c4 * 4 + 2], acc[c4 * 4 + 3]);
}

// ---------------- tf32 MMA GEMM: Y[n,CO] = relu(X*scale+shift)[n,K] @ W[K,CO] + b -------
// BM=128 BN=64 BK=32, 256 threads = 8 warps (4 m-warps x 2 n-warps), each warp 32x32.
// EPI=0: store Y.  EPI=1: atomicMax scatter into segment buffer (layer 4).
template <int EPI>
__global__ void __launch_bounds__(256) gemm_mma(
    const float* __restrict__ X, int K,
    const float* __restrict__ scale, const float* __restrict__ shift,
    const float* __restrict__ W, int CO, const float* __restrict__ bias,
    float* __restrict__ Y, const int* __restrict__ xy, unsigned* __restrict__ seg, int n) {
    __shared__ unsigned As[128 * 36];   // [m][k], stride 36
    __shared__ unsigned Bs[32 * 68];    // [k][n], stride 68
    __shared__ int ids[128];
    extern __shared__ float dyn[];
    float* scs = dyn;
    float* shs = dyn + K;

    const int tid = threadIdx.x;
    const int lane = tid & 31;
    const int wid = tid >> 5;
    const int row0 = blockIdx.y * 128;
    const int col0 = blockIdx.x * 64;
    const int m0 = (wid & 3) * 32;     // warp row offset in tile
    const int n0 = (wid >> 2) * 32;    // warp col offset in tile

    for (int i = tid; i < K; i += 256) { scs[i] = scale[i]; shs[i] = shift[i]; }
    if (EPI == 1 && tid < 128) {
        int gr = row0 + tid;
        ids[tid] = (gr < n) ? (xy[(size_t)gr * 2] * GYD + xy[(size_t)gr * 2 + 1]) : 0;
    }
    __syncthreads();

    float acc[2][4][4] = {};

    for (int k0 = 0; k0 < K; k0 += 32) {
        // load A tile: 128 rows x 32 k, bn+relu+tf32, store m-major
#pragma unroll
        for (int l = 0; l < 4; l++) {
            int m = (tid >> 3) + l * 32;
            int k4 = (tid & 7) * 4;
            int gr = row0 + m;
            float4 av = {0.f, 0.f, 0.f, 0.f};
            if (gr < n) av = *(const float4*)&X[(size_t)gr * K + k0 + k4];
            uint4 o;
            o.x = tf32cvt(fmaxf(av.x * scs[k0 + k4 + 0] + shs[k0 + k4 + 0], 0.f));
            o.y = tf32cvt(fmaxf(av.y * scs[k0 + k4 + 1] + shs[k0 + k4 + 1], 0.f));
            o.z = tf32cvt(fmaxf(av.z * scs[k0 + k4 + 2] + shs[k0 + k4 + 2], 0.f));
            o.w = tf32cvt(fmaxf(av.w * scs[k0 + k4 + 3] + shs[k0 + k4 + 3], 0.f));
            *(uint4*)&As[m * 36 + k4] = o;
        }
        // load B tile: 32 k x 64 n
#pragma unroll
        for (int l = 0; l < 2; l++) {
            int k = (tid >> 4) + l * 16;
            int n4 = (tid & 15) * 4;
            float4 bv = *(const float4*)&W[(size_t)(k0 + k) * CO + col0 + n4];
            uint4 o;
            o.x = tf32cvt(bv.x); o.y = tf32cvt(bv.y); o.z = tf32cvt(bv.z); o.w = tf32cvt(bv.w);
            *(uint4*)&Bs[k * 68 + n4] = o;
        }
        __syncthreads();

#pragma unroll
        for (int kq = 0; kq < 4; kq++) {
            int k8 = kq * 8;
            unsigned a[2][4];
#pragma unroll
            for (int mt = 0; mt < 2; mt++) {
                int mr = m0 + mt * 16 + (lane >> 2);
                int kk = k8 + (lane & 3);
                a[mt][0] = As[mr * 36 + kk];
                a[mt][1] = As[(mr + 8) * 36 + kk];
                a[mt][2] = As[mr * 36 + kk + 4];
                a[mt][3] = As[(mr + 8) * 36 + kk + 4];
            }
            unsigned b[4][2];
#pragma unroll
            for (int nt = 0; nt < 4; nt++) {
                int nn = n0 + nt * 8 + (lane >> 2);
                b[nt][0] = Bs[(k8 + (lane & 3)) * 68 + nn];
                b[nt][1] = Bs[(k8 + 4 + (lane & 3)) * 68 + nn];
            }
#pragma unroll
            for (int mt = 0; mt < 2; mt++)
#pragma unroll
                for (int nt = 0; nt < 4; nt++)
                    mma_tf32(acc[mt][nt], a[mt], b[nt]);
        }
        __syncthreads();
    }

    // epilogue: c0=(r,c) c1=(r,c+1) c2=(r+8,c) c3=(r+8,c+1)
#pragma unroll
    for (int mt = 0; mt < 2; mt++) {
#pragma unroll
        for (int nt = 0; nt < 4; nt++) {
            int lr = m0 + mt * 16 + (lane >> 2);
            int col = col0 + n0 + nt * 8 + 2 * (lane & 3);
            float bc0 = __ldg(&bias[col]);
            float bc1 = __ldg(&bias[col + 1]);
            if (EPI == 0) {
                int gr = row0 + lr;
                if (gr < n) {
                    float2 v = make_float2(acc[mt][nt][0] + bc0, acc[mt][nt][1] + bc1);
                    *(float2*)&Y[(size_t)gr * CO + col] = v;
                }
                gr += 8;
                if (gr < n) {
                    float2 v = make_float2(acc[mt][nt][2] + bc0, acc[mt][nt][3] + bc1);
                    *(float2*)&Y[(size_t)gr * CO + col] = v;
                }
            } else {
                int gr = row0 + lr;
                if (gr < n) {
                    unsigned* srow = seg + (size_t)ids[lr] * 512;
                    atomicMax(&srow[col], fenc(acc[mt][nt][0] + bc0));
                    atomicMax(&srow[col + 1], fenc(acc[mt][nt][1] + bc1));
                }
                gr += 8;
                if (gr < n) {
                    unsigned* srow = seg + (size_t)ids[lr + 8] * 512;
                    atomicMax(&srow[col], fenc(acc[mt][nt][2] + bc0));
                    atomicMax(&srow[col + 1], fenc(acc[mt][nt][3] + bc1));
                }
            }
        }
    }
}

// ---------------- occupancy marking ----------------
__global__ void mark_occ(const int* __restrict__ xy, int n) {
    int i = blockIdx.x * 256 + threadIdx.x;
    if (i < n) g_occ[xy[(size_t)i * 2] * GYD + xy[(size_t)i * 2 + 1]] = 1;
}

// ---------------- head (tf32 MMA): relu(max(seg)[NSEG,512] @ W5[512,32] + b5) ----------
// BM=128 BN=32 BK=32, 256 threads = 8 warps, each warp 16 rows x 32 cols.
__global__ void __launch_bounds__(256) head_mma(
    const unsigned* __restrict__ seg, const int* __restrict__ occ,
    const float* __restrict__ W5, const float* __restrict__ b5, float* __restrict__ out) {
    __shared__ unsigned As[128 * 36];   // [m][k]
    __shared__ unsigned Bs[32 * 36];    // [k][n]
    __shared__ int occs[128];
    __shared__ float b5s[32];

    const int tid = threadIdx.x;
    const int lane = tid & 31;
    const int wid = tid >> 5;
    const int row0 = blockIdx.x * 128;
    const int m0 = wid * 16;

    if (tid < 128) occs[tid] = occ[row0 + tid];
    if (tid < 32) b5s[tid] = b5[tid];
    __syncthreads();

    float acc[4][4] = {};

    for (int k0 = 0; k0 < 512; k0 += 32) {
        // A: 128 rows x 32 k from seg keys (masked decode), tf32, m-major
#pragma unroll
        for (int l = 0; l < 4; l++) {
            int m = (tid >> 3) + l * 32;
            int k4 = (tid & 7) * 4;
            uint4 kv = *(const uint4*)&seg[(size_t)(row0 + m) * 512 + k0 + k4];
            uint4 o;
            if (occs[m]) {
                o.x = tf32cvt(fdec(kv.x)); o.y = tf32cvt(fdec(kv.y));
                o.z = tf32cvt(fdec(kv.z)); o.w = tf32cvt(fdec(kv.w));
            } else {
                o.x = o.y = o.z = o.w = 0u;
            }
            *(uint4*)&As[m * 36 + k4] = o;
        }
        // B: 32 k x 32 n
        {
            int k = tid >> 3;
            int n4 = (tid & 7) * 4;
            float4 bv = *(const float4*)&W5[(size_t)(k0 + k) * 32 + n4];
            uint4 o;
            o.x = tf32cvt(bv.x); o.y = tf32cvt(bv.y); o.z = tf32cvt(bv.z); o.w = tf32cvt(bv.w);
            *(uint4*)&Bs[k * 36 + n4] = o;
        }
        __syncthreads();

#pragma unroll
        for (int kq = 0; kq < 4; kq++) {
            int k8 = kq * 8;
            unsigned a[4];
            int mr = m0 + (lane >> 2);
            int kk = k8 + (lane & 3);
            a[0] = As[mr * 36 + kk];
            a[1] = As[(mr + 8) * 36 + kk];
            a[2] = As[mr * 36 + kk + 4];
            a[3] = As[(mr + 8) * 36 + kk + 4];
            unsigned b[4][2];
#pragma unroll
            for (int nt = 0; nt < 4; nt++) {
                int nn = nt * 8 + (lane >> 2);
                b[nt][0] = Bs[(k8 + (lane & 3)) * 36 + nn];
                b[nt][1] = Bs[(k8 + 4 + (lane & 3)) * 36 + nn];
            }
#pragma unroll
            for (int nt = 0; nt < 4; nt++)
                mma_tf32(acc[nt], a, b[nt]);
        }
        __syncthreads();
    }

#pragma unroll
    for (int nt = 0; nt < 4; nt++) {
        int lr = m0 + (lane >> 2);
        int col = nt * 8 + 2 * (lane & 3);
        int gr = row0 + lr;
        float v0 = occs[lr] ? fmaxf(acc[nt][0] + b5s[col], 0.f) : 0.f;
        float v1 = occs[lr] ? fmaxf(acc[nt][1] + b5s[col + 1], 0.f) : 0.f;
        out[(size_t)col * NSEG + gr] = v0;
        out[(size_t)(col + 1) * NSEG + gr] = v1;
        float v2 = occs[lr + 8] ? fmaxf(acc[nt][2] + b5s[col], 0.f) : 0.f;
        float v3 = occs[lr + 8] ? fmaxf(acc[nt][3] + b5s[col + 1], 0.f) : 0.f;
        out[(size_t)col * NSEG + gr + 8] = v2;
        out[(size_t)(col + 1) * NSEG + gr + 8] = v3;
    }
}

// ---------------- host orchestration ----------------
extern "C" void kernel_launch(void* const* d_in, const int* in_sizes, int n_in,
                              void* d_out, int out_size) {
    const float* pt   = (const float*)d_in[0];
    const int*   xy   = (const int*)d_in[1];
    const float* bn0g = (const float*)d_in[2];
    const float* bn0b = (const float*)d_in[3];
    const float* W1   = (const float*)d_in[4];
    const float* b1   = (const float*)d_in[5];
    const float* bn1g = (const float*)d_in[6];
    const float* bn1b = (const float*)d_in[7];
    const float* W2   = (const float*)d_in[8];
    const float* b2   = (const float*)d_in[9];
    const float* bn2g = (const float*)d_in[10];
    const float* bn2b = (const float*)d_in[11];
    const float* W3   = (const float*)d_in[12];
    const float* b3   = (const float*)d_in[13];
    const float* bn3g = (const float*)d_in[14];
    const float* bn3b = (const float*)d_in[15];
    const float* W4   = (const float*)d_in[16];
    const float* b4   = (const float*)d_in[17];
    const float* W5   = (const float*)d_in[18];
    const float* b5   = (const float*)d_in[19];

    int B = out_size / (NHD * NSEG);
    if (B < 1) B = 1;
    int n = in_sizes[0] / (B * 7);
    float invn = 1.f / (float)n;

    float *y1, *y2, *y3, *sum, *sq, *sc, *sh;
    unsigned* seg;
    int* occ;
    cudaGetSymbolAddress((void**)&y1, g_y1);
    cudaGetSymbolAddress((void**)&y2, g_y2);
    cudaGetSymbolAddress((void**)&y3, g_y3);
    cudaGetSymbolAddress((void**)&seg, g_seg);
    cudaGetSymbolAddress((void**)&occ, g_occ);
    cudaGetSymbolAddress((void**)&sum, g_sum);
    cudaGetSymbolAddress((void**)&sq, g_sq);
    cudaGetSymbolAddress((void**)&sc, g_scale);
    cudaGetSymbolAddress((void**)&sh, g_shift);

    int nb128 = (n + 127) / 128;

    for (int b = 0; b < B; b++) {
        const float* fea = pt + (size_t)b * n * 7;
        const int* xyb = xy + (size_t)b * n * 2;
        float* outb = (float*)d_out + (size_t)b * NHD * NSEG;

        clear_kernel<<<4096, 256>>>();

        // bn0 stats
        colstats_kernel<<<512, 224>>>(fea, n, 7, sum + 0, sq + 0);
        finalize_kernel<<<1, 32>>>(sum + 0, sq + 0, bn0g, bn0b, sc + 0, sh + 0, 7, invn);

        // layer 1: 7 -> 64 (fp32 SIMT, tiny)
        gemm1_kernel<<<(n + 255) / 256, 256>>>(fea, sc + 0, sh + 0, W1, b1, y1, n);
        colstats_kernel<<<512, 256>>>(y1, n, 64, sum + 7, sq + 7);
        finalize_kernel<<<1, 64>>>(sum + 7, sq + 7, bn1g, bn1b, sc + 7, sh + 7, 64, invn);

        // layer 2: 64 -> 128 (tf32 mma)
        gemm_mma<0><<<dim3(2, nb128), 256, 2 * 64 * sizeof(float)>>>(
            y1, 64, sc + 7, sh + 7, W2, 128, b2, y2, nullptr, nullptr, n);
        colstats_kernel<<<512, 256>>>(y2, n, 128, sum + 71, sq + 71);
        finalize_kernel<<<1, 128>>>(sum + 71, sq + 71, bn2g, bn2b, sc + 71, sh + 71, 128, invn);

        // layer 3: 128 -> 256 (tf32 mma)
        gemm_mma<0><<<dim3(4, nb128), 256, 2 * 128 * sizeof(float)>>>(
            y2, 128, sc + 71, sh + 71, W3, 256, b3, y3, nullptr, nullptr, n);
        colstats_kernel<<<512, 256>>>(y3, n, 256, sum + 199, sq + 199);
        finalize_kernel<<<2, 128>>>(sum + 199, sq + 199, bn3g, bn3b, sc + 199, sh + 199, 256, invn);

        // occupancy + layer 4 (256 -> 512, tf32 mma) with fused segment-max scatter
        mark_occ<<<(n + 255) / 256, 256>>>(xyb, n);
        gemm_mma<1><<<dim3(8, nb128), 256, 2 * 256 * sizeof(float)>>>(
            y3, 256, sc + 199, sh + 199, W4, 512, b4, nullptr, xyb, seg, n);

        // head: 512 -> 32 (tf32 mma), masked, transposed write
        head_mma<<<NSEG / 128, 256>>>(seg, occ, W5, b5, outb);
    }
}